// round 10
// baseline (speedup 1.0000x reference)
#include <cuda_runtime.h>

#define NT 128
#define ST 72

__device__ float g_np[5 * 4352];

__device__ __forceinline__ float f2tf(float x) {
    unsigned r;
    asm("cvt.rna.tf32.f32 %0, %1;" : "=r"(r) : "f"(x));
    return __uint_as_float(r);
}

// NP: element (k,n) of 64x64 -> float2 idx (4*(k>>3)+(k&3))*68 + n, comp (k>>2)&1
__global__ void conv_kernel(const float* __restrict__ W1, const float* __restrict__ W2,
                            const float* __restrict__ W3, const float* __restrict__ Wf1) {
    int idx = blockIdx.x * 256 + threadIdx.x;
    if (idx >= 5 * 4096) return;
    int m = idx >> 12, e = idx & 4095, k = e >> 6, n = e & 63;
    float v;
    if (m == 0) v = W1[k * 64 + n];
    else if (m == 1) v = W2[k * 64 + n];
    else if (m == 2) v = W3[k * 64 + n];
    else if (m == 3) v = Wf1[k * 128 + n];
    else v = Wf1[k * 128 + 64 + n];
    g_np[m * 4352 + 2 * ((4 * (k >> 3) + (k & 3)) * 68 + n) + ((k >> 2) & 1)] = f2tf(v);
}

__device__ __forceinline__ void mma8(float* c, unsigned a0, unsigned a1, unsigned a2, unsigned a3,
                                     unsigned b0, unsigned b1) {
    asm("mma.sync.aligned.m16n8k8.row.col.f32.tf32.tf32.f32 "
        "{%0,%1,%2,%3}, {%4,%5,%6,%7}, {%8,%9}, {%0,%1,%2,%3};"
        : "+f"(c[0]), "+f"(c[1]), "+f"(c[2]), "+f"(c[3])
        : "r"(a0), "r"(a1), "r"(a2), "r"(a3), "r"(b0), "r"(b1));
}

// A: scalar [64][ST] with col^(row&4) swizzle. B: NP float2 [32][68].
__device__ __forceinline__ void gemm_anp(const float* __restrict__ A, const float2* __restrict__ B,
                                         int rb, int gid, int tig, float c[8][4]) {
#pragma unroll
    for (int nt = 0; nt < 8; nt++)
#pragma unroll
        for (int q = 0; q < 4; q++) c[nt][q] = 0.0f;
    const int x4 = gid & 4, ca = tig ^ x4;
    const float* A0 = A + (rb + gid) * ST;
    const float* A1 = A0 + 8 * ST;
    const float2* Bp = B + tig * 68 + gid;
#pragma unroll
    for (int ks = 0; ks < 8; ks++) {
        unsigned a0 = __float_as_uint(A0[ca + 8 * ks]);
        unsigned a1 = __float_as_uint(A1[ca + 8 * ks]);
        unsigned a2 = __float_as_uint(A0[(ca ^ 4) + 8 * ks]);
        unsigned a3 = __float_as_uint(A1[(ca ^ 4) + 8 * ks]);
        const float2* Br = Bp + ks * 272;
#pragma unroll
        for (int nt = 0; nt < 8; nt++) {
            float2 b = Br[8 * nt];
            mma8(c[nt], a0, a1, a2, a3, __float_as_uint(b.x), __float_as_uint(b.y));
        }
    }
}

__device__ __forceinline__ void gemm_rnp(const unsigned af[8][4], const float2* __restrict__ B,
                                         int gid, int tig, float c[8][4]) {
#pragma unroll
    for (int nt = 0; nt < 8; nt++)
#pragma unroll
        for (int q = 0; q < 4; q++) c[nt][q] = 0.0f;
    const float2* Bp = B + tig * 68 + gid;
#pragma unroll
    for (int ks = 0; ks < 8; ks++) {
        const float2* Br = Bp + ks * 272;
#pragma unroll
        for (int nt = 0; nt < 8; nt++) {
            float2 b = Br[8 * nt];
            mma8(c[nt], af[ks][0], af[ks][1], af[ks][2], af[ks][3],
                 __float_as_uint(b.x), __float_as_uint(b.y));
        }
    }
}

__device__ __forceinline__ void stage_cp(float* dst, const float* __restrict__ src, int tid) {
    const float4* s = (const float4*)src;
    float4* d = (float4*)dst;
    for (int i = tid; i < 1088; i += NT) d[i] = s[i];
}

// smem floats: s_h 0(4608) | s_w 4608(4352) | s_aux 8960(4352)
//              s_d 13312(64) s_mean(64) s_sh(128) s_w2(128) s_bias(192) -> 13888
__global__ __launch_bounds__(NT, 4) void pgcn_kernel(
    const float* __restrict__ device_obs, const float* __restrict__ server_obs,
    const float* __restrict__ adjacency,
    const float* __restrict__ W_dev, const float* __restrict__ b_dev,
    const float* __restrict__ W_srv, const float* __restrict__ b_srv,
    const float* __restrict__ b1, const float* __restrict__ b2, const float* __restrict__ b3,
    const float* __restrict__ Wf1, const float* __restrict__ bf1,
    const float* __restrict__ Wf2, const float* __restrict__ bf2,
    float* __restrict__ out)
{
    extern __shared__ float sm[];
    float* s_h    = sm;
    float* s_w    = sm + 4608;
    float* s_aux  = sm + 8960;
    float* s_d    = sm + 13312;
    float* s_mean = sm + 13376;
    float* s_sh   = sm + 13440;
    float* s_w2   = sm + 13568;
    float* s_bias = sm + 13696;

    const int b    = blockIdx.x;
    const int tid  = threadIdx.x;
    const int w    = tid >> 5;
    const int lane = tid & 31;
    const int gid  = lane >> 2;
    const int tig  = lane & 3;
    const int rb   = w << 4;
    const int r0   = rb + gid, r1 = r0 + 8;
    const int x4   = gid & 4;

    // ---- P0: adjacency (unswizzled, stride 68) + embed staging + biases ----
    {
        const float4* adjg = (const float4*)(adjacency + (size_t)b * 4096);
#pragma unroll
        for (int idx = tid; idx < 1024; idx += NT) {
            int row = idx >> 4, jc = (idx & 15) << 2;
            *(float4*)&s_aux[row * 68 + jc] = adjg[idx];
        }
        const float* dob = device_obs + (size_t)b * 882;
        for (int idx = tid; idx < 882; idx += NT) s_w[idx] = dob[idx];
        for (int idx = tid; idx < 896; idx += NT) s_w[896 + idx] = W_dev[idx];
        if (tid < 64) s_w[1792 + tid] = b_dev[tid];
        for (int idx = tid; idx < 192; idx += NT) s_w[1856 + idx] = W_srv[idx];
        if (tid < 64) s_w[2048 + tid] = b_srv[tid];
        if (tid < 64) {
            s_bias[tid] = b1[tid];
            s_bias[64 + tid] = b2[tid];
            s_bias[128 + tid] = b3[tid];
        }
        if (tid < 128) s_w2[tid] = Wf2[tid];
    }
    const float so0 = server_obs[b * 3 + 0];
    const float so1 = server_obs[b * 3 + 1];
    const float so2 = server_obs[b * 3 + 2];
    const float bf2v = bf2[0];
    __syncthreads();

    // ---- degree + adjacency A-frag register cache ----
    if (tid < 64) {
        float s = 0.0f;
#pragma unroll
        for (int jc = 0; jc < 16; jc++) {
            float4 v = *(const float4*)&s_aux[tid * 68 + (jc << 2)];
            s += (v.x + v.y) + (v.z + v.w);
        }
        s_d[tid] = rsqrtf(fmaxf(s, 1.0f));
    }
    unsigned af[8][4];
    {
        const float* A0 = s_aux + r0 * 68;
        const float* A1 = s_aux + r1 * 68;
#pragma unroll
        for (int ks = 0; ks < 8; ks++) {
            af[ks][0] = __float_as_uint(A0[tig + 8 * ks]);
            af[ks][1] = __float_as_uint(A1[tig + 8 * ks]);
            af[ks][2] = __float_as_uint(A0[tig + 4 + 8 * ks]);
            af[ks][3] = __float_as_uint(A1[tig + 4 + 8 * ks]);
        }
    }
    __syncthreads();

    // ---- embed: x -> s_h (tf32, ST=72, col^(row&4)) ----
    {
        const float* s_obs = s_w;
        const float* s_wd = s_w + 896;
        const float* s_bd = s_w + 1792;
        const float* s_ws = s_w + 1856;
        const float* s_bs = s_w + 2048;
        for (int idx = tid; idx < 4096; idx += NT) {
            int i = idx >> 6, j = idx & 63;
            float acc;
            if (i < 63) {
                acc = s_bd[j];
                const float* o = s_obs + i * 14;
#pragma unroll
                for (int k = 0; k < 14; k++)
                    acc = fmaf(o[k], s_wd[k * 64 + j], acc);
            } else {
                acc = s_bs[j];
                acc = fmaf(so0, s_ws[j], acc);
                acc = fmaf(so1, s_ws[64 + j], acc);
                acc = fmaf(so2, s_ws[128 + j], acc);
            }
            s_h[i * ST + (j ^ (i & 4))] = f2tf(fmaxf(acc, 0.0f));
        }
    }
    __syncthreads();

    stage_cp(s_w, g_np, tid);   // W1 (NP)
    __syncthreads();

    const float dr0 = s_d[r0], dr1 = s_d[r1];
    // epi-A NP store base: row r0 -> pair-row 8w+(gid&3), comp gid>>2; r1 -> +4 pair-rows
    float* ga0 = s_aux + (8 * w + (gid & 3)) * 136 + (gid >> 2);
    float* ga1 = ga0 + 544;

    // ---- 3 GCN layers: h' = relu(D·A·(D·(h@W)) + b) ----
#pragma unroll 1
    for (int L = 0; L < 3; L++) {
        float c[8][4];
        gemm_anp(s_h, (const float2*)s_w, rb, gid, tig, c);   // g = h @ W_L
#pragma unroll
        for (int nt = 0; nt < 8; nt++) {                      // g' = d_k*g -> s_aux (NP)
            int o = 16 * nt + 4 * tig;
            ga0[o]     = f2tf(c[nt][0] * dr0);
            ga0[o + 2] = f2tf(c[nt][1] * dr0);
            ga1[o]     = f2tf(c[nt][2] * dr1);
            ga1[o + 2] = f2tf(c[nt][3] * dr1);
        }
        __syncthreads();

        gemm_rnp(af, (const float2*)s_aux, gid, tig, c);      // C2 = adj @ g'
        stage_cp(s_w, g_np + (L + 1) * 4352, tid);            // W2, W3, Wf1a
        __syncthreads();

        const float* sb = s_bias + 64 * L;
#pragma unroll
        for (int nt = 0; nt < 8; nt++) {                      // h' = relu(d_i*C2 + b)
            int j = 8 * nt + 2 * tig;
            float bx = sb[j], by = sb[j + 1];
            int pc = j ^ x4;
            *(float2*)&s_h[r0 * ST + pc] =
                make_float2(f2tf(fmaxf(fmaf(dr0, c[nt][0], bx), 0.0f)),
                            f2tf(fmaxf(fmaf(dr0, c[nt][1], by), 0.0f)));
            *(float2*)&s_h[r1 * ST + pc] =
                make_float2(f2tf(fmaxf(fmaf(dr1, c[nt][2], bx), 0.0f)),
                            f2tf(fmaxf(fmaf(dr1, c[nt][3], by), 0.0f)));
        }
        __syncwarp();
    }
    __syncthreads();

    // ---- dev_mean ; stage Wf1b (NP) into s_aux ----
    if (tid < 64) {
        float s = 0.0f;
#pragma unroll 7
        for (int r = 0; r < 63; r++) s += s_h[r * ST + (tid ^ (r & 4))];
        s_mean[tid] = s * (1.0f / 63.0f);
    }
    stage_cp(s_aux, g_np + 4 * 4352, tid);
    __syncthreads();

    // ---- shared head vector: bf1 + mean@Wf1[64:128] + srv@Wf1[128:192] (fp32, global) ----
    {
        float acc = bf1[tid];
#pragma unroll 4
        for (int k = 0; k < 64; k++) {
            float srv = s_h[63 * ST + (k ^ 4)];
            acc = fmaf(s_mean[k], Wf1[(64 + k) * 128 + tid], acc);
            acc = fmaf(srv,       Wf1[(128 + k) * 128 + tid], acc);
        }
        s_sh[tid] = acc;
    }
    __syncthreads();

    // ---- head: two 64-col chunks ----
    float p0 = 0.0f, p1 = 0.0f;
#pragma unroll 1
    for (int c2 = 0; c2 < 2; c2++) {
        float c[8][4];
        gemm_anp(s_h, (const float2*)(c2 ? s_aux : s_w), rb, gid, tig, c);
#pragma unroll
        for (int nt = 0; nt < 8; nt++) {
            int col = (c2 << 6) + (nt << 3) + 2 * tig;
            float2 sh = *(const float2*)&s_sh[col];
            float2 w2 = *(const float2*)&s_w2[col];
            p0 = fmaf(fmaxf(c[nt][0] + sh.x, 0.0f), w2.x, p0);
            p0 = fmaf(fmaxf(c[nt][1] + sh.y, 0.0f), w2.y, p0);
            p1 = fmaf(fmaxf(c[nt][2] + sh.x, 0.0f), w2.x, p1);
            p1 = fmaf(fmaxf(c[nt][3] + sh.y, 0.0f), w2.y, p1);
        }
    }

    p0 += __shfl_xor_sync(0xffffffffu, p0, 1, 4);
    p0 += __shfl_xor_sync(0xffffffffu, p0, 2, 4);
    p1 += __shfl_xor_sync(0xffffffffu, p1, 1, 4);
    p1 += __shfl_xor_sync(0xffffffffu, p1, 2, 4);
    if (tig == 0) {
        out[(size_t)b * 63 + r0] = p0 + bf2v;
        if (r1 < 63) out[(size_t)b * 63 + r1] = p1 + bf2v;
    }
}

extern "C" void kernel_launch(void* const* d_in, const int* in_sizes, int n_in,
                              void* d_out, int out_size)
{
    const float* device_obs = (const float*)d_in[0];
    const float* server_obs = (const float*)d_in[1];
    const float* adjacency  = (const float*)d_in[2];
    const float* W_dev = (const float*)d_in[3];
    const float* b_dev = (const float*)d_in[4];
    const float* W_srv = (const float*)d_in[5];
    const float* b_srv = (const float*)d_in[6];
    const float* W1 = (const float*)d_in[7];
    const float* b1 = (const float*)d_in[8];
    const float* W2 = (const float*)d_in[9];
    const float* b2 = (const float*)d_in[10];
    const float* W3 = (const float*)d_in[11];
    const float* b3 = (const float*)d_in[12];
    const float* Wf1 = (const float*)d_in[13];
    const float* bf1 = (const float*)d_in[14];
    const float* Wf2 = (const float*)d_in[15];
    const float* bf2 = (const float*)d_in[16];

    const int B = in_sizes[0] / (63 * 14);
    conv_kernel<<<(5 * 4096 + 255) / 256, 256>>>(W1, W2, W3, Wf1);
    const size_t smem = 13888 * sizeof(float);
    cudaFuncSetAttribute(pgcn_kernel, cudaFuncAttributeMaxDynamicSharedMemorySize, (int)smem);
    pgcn_kernel<<<B, NT, smem>>>(
        device_obs, server_obs, adjacency,
        W_dev, b_dev, W_srv, b_srv,
        b1, b2, b3, Wf1, bf1, Wf2, bf2,
        (float*)d_out);
}

// round 11
// speedup vs baseline: 1.5416x; 1.5416x over previous
#include <cuda_runtime.h>

#define NT 128
#define ST 72   // 72 ≡ 8 (mod 32): with col^=(row&4) swizzle all frag accesses conflict-free
#define ET 17   // embed tile stride

__device__ __forceinline__ float f2tf(float x) {
    unsigned r;
    asm("cvt.rna.tf32.f32 %0, %1;" : "=r"(r) : "f"(x));
    return __uint_as_float(r);
}

__device__ __forceinline__ void mma8(float* c, unsigned a0, unsigned a1, unsigned a2, unsigned a3,
                                     unsigned b0, unsigned b1) {
    asm("mma.sync.aligned.m16n8k8.row.col.f32.tf32.tf32.f32 "
        "{%0,%1,%2,%3}, {%4,%5,%6,%7}, {%8,%9}, {%0,%1,%2,%3};"
        : "+f"(c[0]), "+f"(c[1]), "+f"(c[2]), "+f"(c[3])
        : "r"(a0), "r"(a1), "r"(a2), "r"(a3), "r"(b0), "r"(b1));
}

// C(16w..16w+15, 0..63) += A(swizzled smem) @ B(swizzled smem)
__device__ __forceinline__ void gemm_ss(const float* __restrict__ A, const float* __restrict__ B,
                                        int rb, int gid, int tig, float c[8][4]) {
#pragma unroll
    for (int nt = 0; nt < 8; nt++)
#pragma unroll
        for (int q = 0; q < 4; q++) c[nt][q] = 0.0f;

    const int x4 = gid & 4;
    const int ca = tig ^ x4;
    const float* A0 = A + (rb + gid) * ST;
    const float* A1 = A0 + 8 * ST;
    const float* B0 = B + tig * ST;
    const float* B1 = B + (tig + 4) * ST;
    const int g0 = gid, g1 = gid ^ 4;
#pragma unroll
    for (int ks = 0; ks < 8; ks++) {
        unsigned a0 = __float_as_uint(A0[ca + 8 * ks]);
        unsigned a1 = __float_as_uint(A1[ca + 8 * ks]);
        unsigned a2 = __float_as_uint(A0[(ca ^ 4) + 8 * ks]);
        unsigned a3 = __float_as_uint(A1[(ca ^ 4) + 8 * ks]);
        const float* b0r = B0 + 8 * ks * ST;
        const float* b1r = B1 + 8 * ks * ST;
#pragma unroll
        for (int nt = 0; nt < 8; nt++) {
            unsigned b0 = __float_as_uint(b0r[g0 + 8 * nt]);
            unsigned b1 = __float_as_uint(b1r[g1 + 8 * nt]);
            mma8(c[nt], a0, a1, a2, a3, b0, b1);
        }
    }
}

// A-fragments (binary adjacency) cached in registers.
__device__ __forceinline__ void gemm_rs(const unsigned af[8][4], const float* __restrict__ B,
                                        int gid, int tig, float c[8][4]) {
#pragma unroll
    for (int nt = 0; nt < 8; nt++)
#pragma unroll
        for (int q = 0; q < 4; q++) c[nt][q] = 0.0f;

    const float* B0 = B + tig * ST;
    const float* B1 = B + (tig + 4) * ST;
    const int g0 = gid, g1 = gid ^ 4;
#pragma unroll
    for (int ks = 0; ks < 8; ks++) {
        const float* b0r = B0 + 8 * ks * ST;
        const float* b1r = B1 + 8 * ks * ST;
#pragma unroll
        for (int nt = 0; nt < 8; nt++) {
            unsigned b0 = __float_as_uint(b0r[g0 + 8 * nt]);
            unsigned b1 = __float_as_uint(b1r[g1 + 8 * nt]);
            mma8(c[nt], af[ks][0], af[ks][1], af[ks][2], af[ks][3], b0, b1);
        }
    }
}

__device__ __forceinline__ void stage_w(float* dst, const float* __restrict__ src,
                                        int stride, int coff, int tid) {
    for (int idx = tid; idx < 1024; idx += NT) {
        int k = idx >> 4, jc = (idx & 15) << 2;
        float4 v = *(const float4*)(src + k * stride + coff + jc);
        v.x = f2tf(v.x); v.y = f2tf(v.y); v.z = f2tf(v.z); v.w = f2tf(v.w);
        *(float4*)&dst[k * ST + (jc ^ (k & 4))] = v;
    }
}

// smem floats: s_h 0(4608) | s_w 4608(4608) | s_aux 9216(4608)
//              s_d 13824(64) s_mean(64) s_sh(128) s_w2(128)  -> 14208 (56832 B, 4 CTAs/SM)
__global__ __launch_bounds__(NT, 4) void pgcn_kernel(
    const float* __restrict__ device_obs, const float* __restrict__ server_obs,
    const float* __restrict__ adjacency,
    const float* __restrict__ W_dev, const float* __restrict__ b_dev,
    const float* __restrict__ W_srv, const float* __restrict__ b_srv,
    const float* __restrict__ W1, const float* __restrict__ b1,
    const float* __restrict__ W2, const float* __restrict__ b2,
    const float* __restrict__ W3, const float* __restrict__ b3,
    const float* __restrict__ Wf1, const float* __restrict__ bf1,
    const float* __restrict__ Wf2, const float* __restrict__ bf2,
    float* __restrict__ out)
{
    extern __shared__ float sm[];
    float* s_h    = sm;                 // activations; tails rows 24..47 cols 64..71 hold b1..b3
    float* s_w    = sm + 4608;          // embed tiles, then staged weights
    float* s_aux  = sm + 9216;          // adjacency (swizzled), then Wf1 chunk1
    float* s_d    = sm + 13824;
    float* s_mean = sm + 13888;         // b_dev during embed, then dev_mean
    float* s_sh   = sm + 13952;
    float* s_w2   = sm + 14080;

    const int b    = blockIdx.x;
    const int tid  = threadIdx.x;
    const int w    = tid >> 5;
    const int lane = tid & 31;
    const int gid  = lane >> 2;
    const int tig  = lane & 3;
    const int rb   = w << 4;
    const int r0   = rb + gid, r1 = r0 + 8;
    const int x4   = gid & 4;

    // ---- P0: adjacency (swizzled), raw obs -> s_h, zero s_w, biases ----
    {
        const float4* adjg = (const float4*)(adjacency + (size_t)b * 4096);
#pragma unroll
        for (int idx = tid; idx < 1024; idx += NT) {
            int row = idx >> 4, jc = (idx & 15) << 2;
            *(float4*)&s_aux[row * ST + (jc ^ (row & 4))] = adjg[idx];
        }
        const float* dob = device_obs + (size_t)b * 882;
        for (int idx = tid; idx < 882; idx += NT) s_h[idx] = dob[idx];
        float4 z = make_float4(0.f, 0.f, 0.f, 0.f);
        float4* zw = (float4*)s_w;
        for (int i = tid; i < 1088; i += NT) zw[i] = z;   // zero embed tile area (4352)
        if (tid < 64) {
            s_mean[tid] = b_dev[tid];
            // biases in s_h tails, rows 24..47, cols 64..71 (indices >= 1792, clear of obs)
            s_h[(24 + (tid >> 3)) * ST + 64 + (tid & 7)] = b1[tid];
            s_h[(32 + (tid >> 3)) * ST + 64 + (tid & 7)] = b2[tid];
            s_h[(40 + (tid >> 3)) * ST + 64 + (tid & 7)] = b3[tid];
        }
        if (tid < 128) s_w2[tid] = Wf2[tid];
    }
    const float so0 = server_obs[b * 3 + 0];
    const float so1 = server_obs[b * 3 + 1];
    const float so2 = server_obs[b * 3 + 2];
    const float bf2v = bf2[0];
    __syncthreads();

    // ---- degree ; build hi/lo embed tiles in s_w ----
    if (tid < 64) {
        float s = 0.0f;
#pragma unroll
        for (int jc = 0; jc < 16; jc++) {
            float4 v = *(const float4*)&s_aux[tid * ST + (jc << 2)];
            s += (v.x + v.y) + (v.z + v.w);
        }
        s_d[tid] = rsqrtf(fmaxf(s, 1.0f));
    }
    {
        // obs tiles: hi [0,1088), lo [1088,2176): [row 0..62][k 0..13], stride 17
        for (int idx = tid; idx < 882; idx += NT) {
            float v = s_h[idx];
            int i = idx / 14, k = idx - i * 14;
            float hi = f2tf(v);
            s_w[i * ET + k] = hi;
            s_w[1088 + i * ET + k] = f2tf(v - hi);
        }
        // WdevT tiles: hi [2176,3264), lo [3264,4352): [n 0..63][k 0..13]
        for (int idx = tid; idx < 896; idx += NT) {
            float v = W_dev[idx];
            int k = idx >> 6, n = idx & 63;
            float hi = f2tf(v);
            s_w[2176 + n * ET + k] = hi;
            s_w[3264 + n * ET + k] = f2tf(v - hi);
        }
    }
    __syncthreads();

    // ---- embed via MMA (hi/lo compensated): x = relu(obs @ Wdev + b_dev) ----
    {
        const float* oh = s_w;
        const float* ol = s_w + 1088;
        const float* th = s_w + 2176;
        const float* tl = s_w + 3264;
        float c[8][4];
#pragma unroll
        for (int nt = 0; nt < 8; nt++)
#pragma unroll
            for (int q = 0; q < 4; q++) c[nt][q] = 0.0f;

#pragma unroll
        for (int ks = 0; ks < 2; ks++) {
            int ck = tig + 8 * ks;
            unsigned ah0 = __float_as_uint(oh[r0 * ET + ck]);
            unsigned ah1 = __float_as_uint(oh[r1 * ET + ck]);
            unsigned ah2 = __float_as_uint(oh[r0 * ET + ck + 4]);
            unsigned ah3 = __float_as_uint(oh[r1 * ET + ck + 4]);
            unsigned al0 = __float_as_uint(ol[r0 * ET + ck]);
            unsigned al1 = __float_as_uint(ol[r1 * ET + ck]);
            unsigned al2 = __float_as_uint(ol[r0 * ET + ck + 4]);
            unsigned al3 = __float_as_uint(ol[r1 * ET + ck + 4]);
#pragma unroll
            for (int nt = 0; nt < 8; nt++) {
                int n = gid + 8 * nt;
                unsigned bh0 = __float_as_uint(th[n * ET + ck]);
                unsigned bh1 = __float_as_uint(th[n * ET + ck + 4]);
                unsigned bl0 = __float_as_uint(tl[n * ET + ck]);
                unsigned bl1 = __float_as_uint(tl[n * ET + ck + 4]);
                mma8(c[nt], ah0, ah1, ah2, ah3, bh0, bh1);
                mma8(c[nt], al0, al1, al2, al3, bh0, bh1);
                mma8(c[nt], ah0, ah1, ah2, ah3, bl0, bl1);
            }
        }
        // epilogue: relu(c + b_dev) -> s_h (tf32, swizzled)
#pragma unroll
        for (int nt = 0; nt < 8; nt++) {
            int j = 8 * nt + 2 * tig;
            float bx = s_mean[j], by = s_mean[j + 1];
            int pc = j ^ x4;
            *(float2*)&s_h[r0 * ST + pc] =
                make_float2(f2tf(fmaxf(c[nt][0] + bx, 0.0f)), f2tf(fmaxf(c[nt][1] + by, 0.0f)));
            *(float2*)&s_h[r1 * ST + pc] =
                make_float2(f2tf(fmaxf(c[nt][2] + bx, 0.0f)), f2tf(fmaxf(c[nt][3] + by, 0.0f)));
        }
    }
    __syncthreads();

    // ---- server row fix ; adjacency A-frag cache ; stage W1 ----
    if (tid < 64) {
        float acc = b_srv[tid];
        acc = fmaf(so0, W_srv[tid], acc);
        acc = fmaf(so1, W_srv[64 + tid], acc);
        acc = fmaf(so2, W_srv[128 + tid], acc);
        s_h[63 * ST + (tid ^ 4)] = f2tf(fmaxf(acc, 0.0f));
    }
    unsigned af[8][4];
    {
        const float* A0 = s_aux + r0 * ST;
        const float* A1 = s_aux + r1 * ST;
        const int ca = tig ^ x4;
#pragma unroll
        for (int ks = 0; ks < 8; ks++) {
            af[ks][0] = __float_as_uint(A0[ca + 8 * ks]);
            af[ks][1] = __float_as_uint(A1[ca + 8 * ks]);
            af[ks][2] = __float_as_uint(A0[(ca ^ 4) + 8 * ks]);
            af[ks][3] = __float_as_uint(A1[(ca ^ 4) + 8 * ks]);
        }
    }
    stage_w(s_w, W1, 64, 0, tid);
    __syncthreads();

    const float dr0 = s_d[r0], dr1 = s_d[r1];
    const int pc0 = 2 * tig;

    // ---- 3 GCN layers: h' = relu(D·A·(D·(h@W)) + b) ----
    const float* stage_src[3] = {W2, W3, Wf1};
    const int    stage_str[3] = {64, 64, 128};
#pragma unroll 1
    for (int L = 0; L < 3; L++) {
        float c[8][4];
        gemm_ss(s_h, s_w, rb, gid, tig, c);                    // g = h @ W_L
#pragma unroll
        for (int nt = 0; nt < 8; nt++) {                       // g' = d_k*g (own rows)
            int pc = ((nt << 3) + pc0) ^ x4;
            *(float2*)&s_h[r0 * ST + pc] = make_float2(f2tf(c[nt][0] * dr0), f2tf(c[nt][1] * dr0));
            *(float2*)&s_h[r1 * ST + pc] = make_float2(f2tf(c[nt][2] * dr1), f2tf(c[nt][3] * dr1));
        }
        __syncthreads();

        gemm_rs(af, s_h, gid, tig, c);                         // C2 = adj @ g'
        stage_w(s_w, stage_src[L], stage_str[L], 0, tid);      // W2, W3, Wf1a
        __syncthreads();

#pragma unroll
        for (int nt = 0; nt < 8; nt++) {                       // h' = relu(d_i*C2 + b_L)
            int j = (nt << 3) + pc0;
            float bx = s_h[(24 + 8 * L + (j >> 3)) * ST + 64 + (j & 7)];
            float by = s_h[(24 + 8 * L + ((j + 1) >> 3)) * ST + 64 + ((j + 1) & 7)];
            int pc = j ^ x4;
            *(float2*)&s_h[r0 * ST + pc] =
                make_float2(f2tf(fmaxf(fmaf(dr0, c[nt][0], bx), 0.0f)),
                            f2tf(fmaxf(fmaf(dr0, c[nt][1], by), 0.0f)));
            *(float2*)&s_h[r1 * ST + pc] =
                make_float2(f2tf(fmaxf(fmaf(dr1, c[nt][2], bx), 0.0f)),
                            f2tf(fmaxf(fmaf(dr1, c[nt][3], by), 0.0f)));
        }
        __syncwarp();
    }
    __syncthreads();

    // ---- dev_mean ; stage Wf1 chunk1 into s_aux ----
    if (tid < 64) {
        float s = 0.0f;
#pragma unroll 7
        for (int r = 0; r < 63; r++) s += s_h[r * ST + (tid ^ (r & 4))];
        s_mean[tid] = s * (1.0f / 63.0f);
    }
    stage_w(s_aux, Wf1, 128, 64, tid);
    __syncthreads();

    // ---- shared head vector: bf1 + mean@Wf1[64:128] + srv@Wf1[128:192] ----
    {
        float acc = bf1[tid];
#pragma unroll 4
        for (int k = 0; k < 64; k++) {
            float srv = s_h[63 * ST + (k ^ 4)];
            acc = fmaf(s_mean[k], Wf1[(64 + k) * 128 + tid], acc);
            acc = fmaf(srv,       Wf1[(128 + k) * 128 + tid], acc);
        }
        s_sh[tid] = acc;
    }
    __syncthreads();

    // ---- head: two 64-col chunks ----
    float p0 = 0.0f, p1 = 0.0f;
#pragma unroll 1
    for (int c2 = 0; c2 < 2; c2++) {
        float c[8][4];
        gemm_ss(s_h, (c2 ? s_aux : s_w), rb, gid, tig, c);
#pragma unroll
        for (int nt = 0; nt < 8; nt++) {
            int col = (c2 << 6) + (nt << 3) + pc0;
            float2 sh = *(const float2*)&s_sh[col];
            float2 w2 = *(const float2*)&s_w2[col];
            p0 = fmaf(fmaxf(c[nt][0] + sh.x, 0.0f), w2.x, p0);
            p0 = fmaf(fmaxf(c[nt][1] + sh.y, 0.0f), w2.y, p0);
            p1 = fmaf(fmaxf(c[nt][2] + sh.x, 0.0f), w2.x, p1);
            p1 = fmaf(fmaxf(c[nt][3] + sh.y, 0.0f), w2.y, p1);
        }
    }

    p0 += __shfl_xor_sync(0xffffffffu, p0, 1, 4);
    p0 += __shfl_xor_sync(0xffffffffu, p0, 2, 4);
    p1 += __shfl_xor_sync(0xffffffffu, p1, 1, 4);
    p1 += __shfl_xor_sync(0xffffffffu, p1, 2, 4);
    if (tig == 0) {
        out[(size_t)b * 63 + r0] = p0 + bf2v;
        if (r1 < 63) out[(size_t)b * 63 + r1] = p1 + bf2v;
    }
}

extern "C" void kernel_launch(void* const* d_in, const int* in_sizes, int n_in,
                              void* d_out, int out_size)
{
    const float* device_obs = (const float*)d_in[0];
    const float* server_obs = (const float*)d_in[1];
    const float* adjacency  = (const float*)d_in[2];
    const float* W_dev = (const float*)d_in[3];
    const float* b_dev = (const float*)d_in[4];
    const float* W_srv = (const float*)d_in[5];
    const float* b_srv = (const float*)d_in[6];
    const float* W1 = (const float*)d_in[7];
    const float* b1 = (const float*)d_in[8];
    const float* W2 = (const float*)d_in[9];
    const float* b2 = (const float*)d_in[10];
    const float* W3 = (const float*)d_in[11];
    const float* b3 = (const float*)d_in[12];
    const float* Wf1 = (const float*)d_in[13];
    const float* bf1 = (const float*)d_in[14];
    const float* Wf2 = (const float*)d_in[15];
    const float* bf2 = (const float*)d_in[16];

    const int B = in_sizes[0] / (63 * 14);
    const size_t smem = 14208 * sizeof(float);
    cudaFuncSetAttribute(pgcn_kernel, cudaFuncAttributeMaxDynamicSharedMemorySize, (int)smem);
    pgcn_kernel<<<B, NT, smem>>>(
        device_obs, server_obs, adjacency,
        W_dev, b_dev, W_srv, b_srv,
        W1, b1, W2, b2, W3, b3,
        Wf1, bf1, Wf2, bf2,
        (float*)d_out);
}

// round 12
// speedup vs baseline: 1.7007x; 1.1032x over previous
#include <cuda_runtime.h>

#define NT 128
#define ST 72   // 72 ≡ 8 (mod 32): with col^=(row&4) swizzle all frag accesses conflict-free
#define ET 17   // embed tile stride

__device__ __forceinline__ float f2tf(float x) {
    unsigned r;
    asm("cvt.rna.tf32.f32 %0, %1;" : "=r"(r) : "f"(x));
    return __uint_as_float(r);
}

__device__ __forceinline__ void mma8(float* c, unsigned a0, unsigned a1, unsigned a2, unsigned a3,
                                     unsigned b0, unsigned b1) {
    asm("mma.sync.aligned.m16n8k8.row.col.f32.tf32.tf32.f32 "
        "{%0,%1,%2,%3}, {%4,%5,%6,%7}, {%8,%9}, {%0,%1,%2,%3};"
        : "+f"(c[0]), "+f"(c[1]), "+f"(c[2]), "+f"(c[3])
        : "r"(a0), "r"(a1), "r"(a2), "r"(a3), "r"(b0), "r"(b1));
}

// C(16w..16w+15, 0..63) += A(swizzled smem) @ B(swizzled smem)
__device__ __forceinline__ void gemm_ss(const float* __restrict__ A, const float* __restrict__ B,
                                        int rb, int gid, int tig, float c[8][4]) {
#pragma unroll
    for (int nt = 0; nt < 8; nt++)
#pragma unroll
        for (int q = 0; q < 4; q++) c[nt][q] = 0.0f;

    const int x4 = gid & 4;
    const int ca = tig ^ x4;
    const float* A0 = A + (rb + gid) * ST;
    const float* A1 = A0 + 8 * ST;
    const float* B0 = B + tig * ST;
    const float* B1 = B + (tig + 4) * ST;
    const int g0 = gid, g1 = gid ^ 4;
#pragma unroll
    for (int ks = 0; ks < 8; ks++) {
        unsigned a0 = __float_as_uint(A0[ca + 8 * ks]);
        unsigned a1 = __float_as_uint(A1[ca + 8 * ks]);
        unsigned a2 = __float_as_uint(A0[(ca ^ 4) + 8 * ks]);
        unsigned a3 = __float_as_uint(A1[(ca ^ 4) + 8 * ks]);
        const float* b0r = B0 + 8 * ks * ST;
        const float* b1r = B1 + 8 * ks * ST;
#pragma unroll
        for (int nt = 0; nt < 8; nt++) {
            unsigned b0 = __float_as_uint(b0r[g0 + 8 * nt]);
            unsigned b1 = __float_as_uint(b1r[g1 + 8 * nt]);
            mma8(c[nt], a0, a1, a2, a3, b0, b1);
        }
    }
}

// A operand = binary adjacency packed as 32 bits in one register (bit ks*4+q).
__device__ __forceinline__ void gemm_rb(unsigned abits, const float* __restrict__ B,
                                        int gid, int tig, float c[8][4]) {
#pragma unroll
    for (int nt = 0; nt < 8; nt++)
#pragma unroll
        for (int q = 0; q < 4; q++) c[nt][q] = 0.0f;

    const float* B0 = B + tig * ST;
    const float* B1 = B + (tig + 4) * ST;
    const int g0 = gid, g1 = gid ^ 4;
#pragma unroll
    for (int ks = 0; ks < 8; ks++) {
        unsigned f = abits >> (4 * ks);
        unsigned a0 = (f & 1u) * 0x3F800000u;
        unsigned a1 = ((f >> 1) & 1u) * 0x3F800000u;
        unsigned a2 = ((f >> 2) & 1u) * 0x3F800000u;
        unsigned a3 = ((f >> 3) & 1u) * 0x3F800000u;
        const float* b0r = B0 + 8 * ks * ST;
        const float* b1r = B1 + 8 * ks * ST;
#pragma unroll
        for (int nt = 0; nt < 8; nt++) {
            unsigned b0 = __float_as_uint(b0r[g0 + 8 * nt]);
            unsigned b1 = __float_as_uint(b1r[g1 + 8 * nt]);
            mma8(c[nt], a0, a1, a2, a3, b0, b1);
        }
    }
}

__device__ __forceinline__ void stage_w(float* dst, const float* __restrict__ src,
                                        int stride, int coff, int tid) {
    for (int idx = tid; idx < 1024; idx += NT) {
        int k = idx >> 4, jc = (idx & 15) << 2;
        float4 v = *(const float4*)(src + k * stride + coff + jc);
        v.x = f2tf(v.x); v.y = f2tf(v.y); v.z = f2tf(v.z); v.w = f2tf(v.w);
        *(float4*)&dst[k * ST + (jc ^ (k & 4))] = v;
    }
}

// smem floats: s_h 0(4608) | s_w 4608(4608) | s_d 9216(64) s_mean(64) s_sh(128) s_w2(128)
//   -> 9600 floats = 38400 B -> 5 CTAs/SM
__global__ __launch_bounds__(NT, 5) void pgcn_kernel(
    const float* __restrict__ device_obs, const float* __restrict__ server_obs,
    const float* __restrict__ adjacency,
    const float* __restrict__ W_dev, const float* __restrict__ b_dev,
    const float* __restrict__ W_srv, const float* __restrict__ b_srv,
    const float* __restrict__ W1, const float* __restrict__ b1,
    const float* __restrict__ W2, const float* __restrict__ b2,
    const float* __restrict__ W3, const float* __restrict__ b3,
    const float* __restrict__ Wf1, const float* __restrict__ bf1,
    const float* __restrict__ Wf2, const float* __restrict__ bf2,
    float* __restrict__ out)
{
    extern __shared__ float sm[];
    float* s_h    = sm;                 // obs staging -> activations; tails rows 24..47 cols 64..71: b1..b3
    float* s_w    = sm + 4608;          // adjacency (stride 68) -> embed tiles -> staged weights
    float* s_d    = sm + 9216;
    float* s_mean = sm + 9280;          // b_dev during embed, then dev_mean
    float* s_sh   = sm + 9344;
    float* s_w2   = sm + 9472;

    const int b    = blockIdx.x;
    const int tid  = threadIdx.x;
    const int w    = tid >> 5;
    const int lane = tid & 31;
    const int gid  = lane >> 2;
    const int tig  = lane & 3;
    const int rb   = w << 4;
    const int r0   = rb + gid, r1 = r0 + 8;
    const int x4   = gid & 4;

    // ---- P0: adjacency -> s_w (plain, stride 68); raw obs -> s_h; biases ----
    {
        const float4* adjg = (const float4*)(adjacency + (size_t)b * 4096);
#pragma unroll
        for (int idx = tid; idx < 1024; idx += NT) {
            int row = idx >> 4, jc = (idx & 15) << 2;
            *(float4*)&s_w[row * 68 + jc] = adjg[idx];
        }
        const float* dob = device_obs + (size_t)b * 882;
        for (int idx = tid; idx < 882; idx += NT) s_h[idx] = dob[idx];
        if (tid < 64) {
            s_mean[tid] = b_dev[tid];
            s_h[(24 + (tid >> 3)) * ST + 64 + (tid & 7)] = b1[tid];
            s_h[(32 + (tid >> 3)) * ST + 64 + (tid & 7)] = b2[tid];
            s_h[(40 + (tid >> 3)) * ST + 64 + (tid & 7)] = b3[tid];
        }
        if (tid < 128) s_w2[tid] = Wf2[tid];
    }
    const float so0 = server_obs[b * 3 + 0];
    const float so1 = server_obs[b * 3 + 1];
    const float so2 = server_obs[b * 3 + 2];
    const float bf2v = bf2[0];
    __syncthreads();

    // ---- degree ; adjacency fragment bitmask ----
    if (tid < 64) {
        float s = 0.0f;
#pragma unroll
        for (int jc = 0; jc < 16; jc++) {
            float4 v = *(const float4*)&s_w[tid * 68 + (jc << 2)];
            s += (v.x + v.y) + (v.z + v.w);
        }
        s_d[tid] = rsqrtf(fmaxf(s, 1.0f));
    }
    unsigned abits = 0u;
    {
        const float* A0 = s_w + r0 * 68;
        const float* A1 = s_w + r1 * 68;
#pragma unroll
        for (int ks = 0; ks < 8; ks++) {
            abits |= (A0[tig + 8 * ks]     != 0.0f ? 1u : 0u) << (4 * ks + 0);
            abits |= (A1[tig + 8 * ks]     != 0.0f ? 1u : 0u) << (4 * ks + 1);
            abits |= (A0[tig + 4 + 8 * ks] != 0.0f ? 1u : 0u) << (4 * ks + 2);
            abits |= (A1[tig + 4 + 8 * ks] != 0.0f ? 1u : 0u) << (4 * ks + 3);
        }
    }
    __syncthreads();   // adjacency fully consumed; s_w reusable

    // ---- build hi/lo embed tiles in s_w (obs from s_h, W_dev from global) ----
    {
        float4 z = make_float4(0.f, 0.f, 0.f, 0.f);
        float4* zw = (float4*)s_w;
        for (int i = tid; i < 1088; i += NT) zw[i] = z;
    }
    __syncthreads();
    {
        for (int idx = tid; idx < 882; idx += NT) {
            float v = s_h[idx];
            int i = idx / 14, k = idx - i * 14;
            float hi = f2tf(v);
            s_w[i * ET + k] = hi;
            s_w[1088 + i * ET + k] = f2tf(v - hi);
        }
        for (int idx = tid; idx < 896; idx += NT) {
            float v = W_dev[idx];
            int k = idx >> 6, n = idx & 63;
            float hi = f2tf(v);
            s_w[2176 + n * ET + k] = hi;
            s_w[3264 + n * ET + k] = f2tf(v - hi);
        }
    }
    __syncthreads();

    // ---- embed via MMA (hi/lo compensated): x = relu(obs @ Wdev + b_dev) ----
    {
        const float* oh = s_w;
        const float* ol = s_w + 1088;
        const float* th = s_w + 2176;
        const float* tl = s_w + 3264;
        float c[8][4];
#pragma unroll
        for (int nt = 0; nt < 8; nt++)
#pragma unroll
            for (int q = 0; q < 4; q++) c[nt][q] = 0.0f;

#pragma unroll
        for (int ks = 0; ks < 2; ks++) {
            int ck = tig + 8 * ks;
            unsigned ah0 = __float_as_uint(oh[r0 * ET + ck]);
            unsigned ah1 = __float_as_uint(oh[r1 * ET + ck]);
            unsigned ah2 = __float_as_uint(oh[r0 * ET + ck + 4]);
            unsigned ah3 = __float_as_uint(oh[r1 * ET + ck + 4]);
            unsigned al0 = __float_as_uint(ol[r0 * ET + ck]);
            unsigned al1 = __float_as_uint(ol[r1 * ET + ck]);
            unsigned al2 = __float_as_uint(ol[r0 * ET + ck + 4]);
            unsigned al3 = __float_as_uint(ol[r1 * ET + ck + 4]);
#pragma unroll
            for (int nt = 0; nt < 8; nt++) {
                int n = gid + 8 * nt;
                unsigned bh0 = __float_as_uint(th[n * ET + ck]);
                unsigned bh1 = __float_as_uint(th[n * ET + ck + 4]);
                unsigned bl0 = __float_as_uint(tl[n * ET + ck]);
                unsigned bl1 = __float_as_uint(tl[n * ET + ck + 4]);
                mma8(c[nt], ah0, ah1, ah2, ah3, bh0, bh1);
                mma8(c[nt], al0, al1, al2, al3, bh0, bh1);
                mma8(c[nt], ah0, ah1, ah2, ah3, bl0, bl1);
            }
        }
#pragma unroll
        for (int nt = 0; nt < 8; nt++) {
            int j = 8 * nt + 2 * tig;
            float bx = s_mean[j], by = s_mean[j + 1];
            int pc = j ^ x4;
            *(float2*)&s_h[r0 * ST + pc] =
                make_float2(f2tf(fmaxf(c[nt][0] + bx, 0.0f)), f2tf(fmaxf(c[nt][1] + by, 0.0f)));
            *(float2*)&s_h[r1 * ST + pc] =
                make_float2(f2tf(fmaxf(c[nt][2] + bx, 0.0f)), f2tf(fmaxf(c[nt][3] + by, 0.0f)));
        }
    }
    __syncthreads();

    // ---- server row fix ; stage W1 ----
    if (tid < 64) {
        float acc = b_srv[tid];
        acc = fmaf(so0, W_srv[tid], acc);
        acc = fmaf(so1, W_srv[64 + tid], acc);
        acc = fmaf(so2, W_srv[128 + tid], acc);
        s_h[63 * ST + (tid ^ 4)] = f2tf(fmaxf(acc, 0.0f));
    }
    stage_w(s_w, W1, 64, 0, tid);
    __syncthreads();

    const float dr0 = s_d[r0], dr1 = s_d[r1];
    const int pc0 = 2 * tig;

    // ---- 3 GCN layers: h' = relu(D·A·(D·(h@W)) + b) ----
    const float* stage_src[3] = {W2, W3, Wf1};
    const int    stage_str[3] = {64, 64, 128};
#pragma unroll 1
    for (int L = 0; L < 3; L++) {
        float c[8][4];
        gemm_ss(s_h, s_w, rb, gid, tig, c);                    // g = h @ W_L
#pragma unroll
        for (int nt = 0; nt < 8; nt++) {                       // g' = d_k*g (own rows)
            int pc = ((nt << 3) + pc0) ^ x4;
            *(float2*)&s_h[r0 * ST + pc] = make_float2(f2tf(c[nt][0] * dr0), f2tf(c[nt][1] * dr0));
            *(float2*)&s_h[r1 * ST + pc] = make_float2(f2tf(c[nt][2] * dr1), f2tf(c[nt][3] * dr1));
        }
        __syncthreads();

        gemm_rb(abits, s_h, gid, tig, c);                      // C2 = adj @ g'
        stage_w(s_w, stage_src[L], stage_str[L], 0, tid);      // W2, W3, Wf1a
        __syncthreads();

#pragma unroll
        for (int nt = 0; nt < 8; nt++) {                       // h' = relu(d_i*C2 + b_L)
            int j = (nt << 3) + pc0;
            float bx = s_h[(24 + 8 * L + (j >> 3)) * ST + 64 + (j & 7)];
            float by = s_h[(24 + 8 * L + ((j + 1) >> 3)) * ST + 64 + ((j + 1) & 7)];
            int pc = j ^ x4;
            *(float2*)&s_h[r0 * ST + pc] =
                make_float2(f2tf(fmaxf(fmaf(dr0, c[nt][0], bx), 0.0f)),
                            f2tf(fmaxf(fmaf(dr0, c[nt][1], by), 0.0f)));
            *(float2*)&s_h[r1 * ST + pc] =
                make_float2(f2tf(fmaxf(fmaf(dr1, c[nt][2], bx), 0.0f)),
                            f2tf(fmaxf(fmaf(dr1, c[nt][3], by), 0.0f)));
        }
        __syncwarp();
    }
    __syncthreads();

    // ---- dev_mean ----
    if (tid < 64) {
        float s = 0.0f;
#pragma unroll 7
        for (int r = 0; r < 63; r++) s += s_h[r * ST + (tid ^ (r & 4))];
        s_mean[tid] = s * (1.0f / 63.0f);
    }
    __syncthreads();

    // ---- shared head vector: bf1 + mean@Wf1[64:128] + srv@Wf1[128:192] ----
    {
        float acc = bf1[tid];
#pragma unroll 4
        for (int k = 0; k < 64; k++) {
            float srv = s_h[63 * ST + (k ^ 4)];
            acc = fmaf(s_mean[k], Wf1[(64 + k) * 128 + tid], acc);
            acc = fmaf(srv,       Wf1[(128 + k) * 128 + tid], acc);
        }
        s_sh[tid] = acc;
    }
    __syncthreads();

    // ---- head: chunk0 (Wf1a already in s_w), restage, chunk1 ----
    float p0 = 0.0f, p1 = 0.0f;
#pragma unroll 1
    for (int c2 = 0; c2 < 2; c2++) {
        float c[8][4];
        gemm_ss(s_h, s_w, rb, gid, tig, c);
#pragma unroll
        for (int nt = 0; nt < 8; nt++) {
            int col = (c2 << 6) + (nt << 3) + pc0;
            float2 sh = *(const float2*)&s_sh[col];
            float2 w2 = *(const float2*)&s_w2[col];
            p0 = fmaf(fmaxf(c[nt][0] + sh.x, 0.0f), w2.x, p0);
            p0 = fmaf(fmaxf(c[nt][1] + sh.y, 0.0f), w2.y, p0);
            p1 = fmaf(fmaxf(c[nt][2] + sh.x, 0.0f), w2.x, p1);
            p1 = fmaf(fmaxf(c[nt][3] + sh.y, 0.0f), w2.y, p1);
        }
        if (c2 == 0) {
            __syncthreads();
            stage_w(s_w, Wf1, 128, 64, tid);   // Wf1 chunk1
            __syncthreads();
        }
    }

    p0 += __shfl_xor_sync(0xffffffffu, p0, 1, 4);
    p0 += __shfl_xor_sync(0xffffffffu, p0, 2, 4);
    p1 += __shfl_xor_sync(0xffffffffu, p1, 1, 4);
    p1 += __shfl_xor_sync(0xffffffffu, p1, 2, 4);
    if (tig == 0) {
        out[(size_t)b * 63 + r0] = p0 + bf2v;
        if (r1 < 63) out[(size_t)b * 63 + r1] = p1 + bf2v;
    }
}

extern "C" void kernel_launch(void* const* d_in, const int* in_sizes, int n_in,
                              void* d_out, int out_size)
{
    const float* device_obs = (const float*)d_in[0];
    const float* server_obs = (const float*)d_in[1];
    const float* adjacency  = (const float*)d_in[2];
    const float* W_dev = (const float*)d_in[3];
    const float* b_dev = (const float*)d_in[4];
    const float* W_srv = (const float*)d_in[5];
    const float* b_srv = (const float*)d_in[6];
    const float* W1 = (const float*)d_in[7];
    const float* b1 = (const float*)d_in[8];
    const float* W2 = (const float*)d_in[9];
    const float* b2 = (const float*)d_in[10];
    const float* W3 = (const float*)d_in[11];
    const float* b3 = (const float*)d_in[12];
    const float* Wf1 = (const float*)d_in[13];
    const float* bf1 = (const float*)d_in[14];
    const float* Wf2 = (const float*)d_in[15];
    const float* bf2 = (const float*)d_in[16];

    const int B = in_sizes[0] / (63 * 14);
    const size_t smem = 9600 * sizeof(float);
    cudaFuncSetAttribute(pgcn_kernel, cudaFuncAttributeMaxDynamicSharedMemorySize, (int)smem);
    pgcn_kernel<<<B, NT, smem>>>(
        device_obs, server_obs, adjacency,
        W_dev, b_dev, W_srv, b_srv,
        W1, b1, W2, b2, W3, b3,
        Wf1, bf1, Wf2, bf2,
        (float*)d_out);
}

// round 16
// speedup vs baseline: 1.7138x; 1.0077x over previous
#include <cuda_runtime.h>

#define NT 128
#define ST 72   // 72 ≡ 8 (mod 32): with col^=(row&4) swizzle all frag accesses conflict-free
#define ET 17   // embed tile stride

// Pre-swizzled tf32 weight images: 0=W1 1=W2 2=W3 3=Wf1a 4=Wf1b (4608 floats each, pads zeroed)
__device__ float g_wsw[5 * 4608];

__device__ __forceinline__ float f2tf(float x) {
    unsigned r;
    asm("cvt.rna.tf32.f32 %0, %1;" : "=r"(r) : "f"(x));
    return __uint_as_float(r);
}

__global__ void prep_kernel(const float* __restrict__ W1, const float* __restrict__ W2,
                            const float* __restrict__ W3, const float* __restrict__ Wf1) {
    int idx = blockIdx.x * 256 + threadIdx.x;
    if (idx >= 5 * 4608) return;
    int m = idx / 4608, o = idx % 4608;
    int k = o / ST, cc = o % ST;
    float v = 0.0f;
    if (cc < 64) {
        int j = cc ^ (k & 4);
        if (m == 0)      v = f2tf(W1[k * 64 + j]);
        else if (m == 1) v = f2tf(W2[k * 64 + j]);
        else if (m == 2) v = f2tf(W3[k * 64 + j]);
        else if (m == 3) v = f2tf(Wf1[k * 128 + j]);
        else             v = f2tf(Wf1[k * 128 + 64 + j]);
    }
    g_wsw[idx] = v;
}

__device__ __forceinline__ void mma8(float* c, unsigned a0, unsigned a1, unsigned a2, unsigned a3,
                                     unsigned b0, unsigned b1) {
    asm("mma.sync.aligned.m16n8k8.row.col.f32.tf32.tf32.f32 "
        "{%0,%1,%2,%3}, {%4,%5,%6,%7}, {%8,%9}, {%0,%1,%2,%3};"
        : "+f"(c[0]), "+f"(c[1]), "+f"(c[2]), "+f"(c[3])
        : "r"(a0), "r"(a1), "r"(a2), "r"(a3), "r"(b0), "r"(b1));
}

// 2x2 warp tiling: warp computes C rows rbm..rbm+31, cols cbn..cbn+31.
__device__ __forceinline__ void gemm_ss(const float* __restrict__ A, const float* __restrict__ B,
                                        int rbm, int cbn, int gid, int tig, float c[2][4][4]) {
#pragma unroll
    for (int mt = 0; mt < 2; mt++)
#pragma unroll
        for (int nt = 0; nt < 4; nt++)
#pragma unroll
            for (int q = 0; q < 4; q++) c[mt][nt][q] = 0.0f;

    const int x4 = gid & 4, ca = tig ^ x4;
    const float* Am0 = A + (rbm + gid) * ST;
    const float* Am1 = A + (rbm + 16 + gid) * ST;
    const float* B0 = B + tig * ST;
    const float* B1 = B + (tig + 4) * ST;
    const int g0 = cbn + gid, g1 = cbn + (gid ^ 4);
#pragma unroll
    for (int ks = 0; ks < 8; ks++) {
        unsigned a00 = __float_as_uint(Am0[ca + 8 * ks]);
        unsigned a01 = __float_as_uint(Am0[8 * ST + ca + 8 * ks]);
        unsigned a02 = __float_as_uint(Am0[(ca ^ 4) + 8 * ks]);
        unsigned a03 = __float_as_uint(Am0[8 * ST + (ca ^ 4) + 8 * ks]);
        unsigned a10 = __float_as_uint(Am1[ca + 8 * ks]);
        unsigned a11 = __float_as_uint(Am1[8 * ST + ca + 8 * ks]);
        unsigned a12 = __float_as_uint(Am1[(ca ^ 4) + 8 * ks]);
        unsigned a13 = __float_as_uint(Am1[8 * ST + (ca ^ 4) + 8 * ks]);
        const float* b0r = B0 + 8 * ks * ST;
        const float* b1r = B1 + 8 * ks * ST;
#pragma unroll
        for (int nt = 0; nt < 4; nt++) {
            unsigned b0 = __float_as_uint(b0r[g0 + 8 * nt]);
            unsigned b1 = __float_as_uint(b1r[g1 + 8 * nt]);
            mma8(c[0][nt], a00, a01, a02, a03, b0, b1);
            mma8(c[1][nt], a10, a11, a12, a13, b0, b1);
        }
    }
}

// A = binary adjacency bits: ab0/ab1 bit (4*ks+q) for the two 16-row m-tiles.
__device__ __forceinline__ void gemm_rb(unsigned ab0, unsigned ab1, const float* __restrict__ B,
                                        int cbn, int gid, int tig, float c[2][4][4]) {
#pragma unroll
    for (int mt = 0; mt < 2; mt++)
#pragma unroll
        for (int nt = 0; nt < 4; nt++)
#pragma unroll
            for (int q = 0; q < 4; q++) c[mt][nt][q] = 0.0f;

    const float* B0 = B + tig * ST;
    const float* B1 = B + (tig + 4) * ST;
    const int g0 = cbn + gid, g1 = cbn + (gid ^ 4);
#pragma unroll
    for (int ks = 0; ks < 8; ks++) {
        unsigned f0 = ab0 >> (4 * ks), f1 = ab1 >> (4 * ks);
        unsigned a00 = (f0 & 1u) * 0x3F800000u;
        unsigned a01 = ((f0 >> 1) & 1u) * 0x3F800000u;
        unsigned a02 = ((f0 >> 2) & 1u) * 0x3F800000u;
        unsigned a03 = ((f0 >> 3) & 1u) * 0x3F800000u;
        unsigned a10 = (f1 & 1u) * 0x3F800000u;
        unsigned a11 = ((f1 >> 1) & 1u) * 0x3F800000u;
        unsigned a12 = ((f1 >> 2) & 1u) * 0x3F800000u;
        unsigned a13 = ((f1 >> 3) & 1u) * 0x3F800000u;
        const float* b0r = B0 + 8 * ks * ST;
        const float* b1r = B1 + 8 * ks * ST;
#pragma unroll
        for (int nt = 0; nt < 4; nt++) {
            unsigned b0 = __float_as_uint(b0r[g0 + 8 * nt]);
            unsigned b1 = __float_as_uint(b1r[g1 + 8 * nt]);
            mma8(c[0][nt], a00, a01, a02, a03, b0, b1);
            mma8(c[1][nt], a10, a11, a12, a13, b0, b1);
        }
    }
}

__device__ __forceinline__ void stage_cp(float* dst, const float* __restrict__ src, int tid) {
    const float4* s = (const float4*)src;
    float4* d = (float4*)dst;
#pragma unroll
    for (int i = tid; i < 1152; i += NT) d[i] = s[i];
}

// smem floats: s_h 0(4608) | s_w 4608(4608) | s_d 9216(64) s_mean(64) s_sh(128) s_w2(128) -> 9600
__global__ __launch_bounds__(NT, 5) void pgcn_kernel(
    const float* __restrict__ device_obs, const float* __restrict__ server_obs,
    const float* __restrict__ adjacency,
    const float* __restrict__ W_dev, const float* __restrict__ b_dev,
    const float* __restrict__ W_srv, const float* __restrict__ b_srv,
    const float* __restrict__ b1, const float* __restrict__ b2, const float* __restrict__ b3,
    const float* __restrict__ Wf1, const float* __restrict__ bf1,
    const float* __restrict__ Wf2, const float* __restrict__ bf2,
    float* __restrict__ out)
{
    extern __shared__ float sm[];
    float* s_h    = sm;
    float* s_w    = sm + 4608;
    float* s_d    = sm + 9216;
    float* s_mean = sm + 9280;   // b_dev during embed -> dev_mean -> head output accum
    float* s_sh   = sm + 9344;
    float* s_w2   = sm + 9472;

    const int b    = blockIdx.x;
    const int tid  = threadIdx.x;
    const int w    = tid >> 5;
    const int wm   = w >> 1, wn = w & 1;
    const int rbm  = wm << 5, cbn = wn << 5;
    const int lane = tid & 31;
    const int gid  = lane >> 2;
    const int tig  = lane & 3;
    const int x4   = gid & 4;
    const int R0 = rbm + gid, R1 = R0 + 8, R2 = R0 + 16, R3 = R0 + 24;

    // ---- P0: adjacency -> s_w (stride 68); raw obs -> s_h; biases ----
    {
        const float4* adjg = (const float4*)(adjacency + (size_t)b * 4096);
#pragma unroll
        for (int idx = tid; idx < 1024; idx += NT) {
            int row = idx >> 4, jc = (idx & 15) << 2;
            *(float4*)&s_w[row * 68 + jc] = adjg[idx];
        }
        const float* dob = device_obs + (size_t)b * 882;
        for (int idx = tid; idx < 882; idx += NT) s_h[idx] = dob[idx];
        if (tid < 64) {
            s_mean[tid] = b_dev[tid];
            s_h[(24 + (tid >> 3)) * ST + 64 + (tid & 7)] = b1[tid];
            s_h[(32 + (tid >> 3)) * ST + 64 + (tid & 7)] = b2[tid];
            s_h[(40 + (tid >> 3)) * ST + 64 + (tid & 7)] = b3[tid];
        }
        if (tid < 128) s_w2[tid] = Wf2[tid];
    }
    const float so0 = server_obs[b * 3 + 0];
    const float so1 = server_obs[b * 3 + 1];
    const float so2 = server_obs[b * 3 + 2];
    const float bf2v = bf2[0];
    __syncthreads();

    // ---- degree ; adjacency bitmasks (2 m-tiles) ----
    if (tid < 64) {
        float s = 0.0f;
#pragma unroll
        for (int jc = 0; jc < 16; jc++) {
            float4 v = *(const float4*)&s_w[tid * 68 + (jc << 2)];
            s += (v.x + v.y) + (v.z + v.w);
        }
        s_d[tid] = rsqrtf(fmaxf(s, 1.0f));
    }
    unsigned ab0 = 0u, ab1 = 0u;
    {
        const float* A00 = s_w + R0 * 68;
        const float* A01 = s_w + R1 * 68;
        const float* A10 = s_w + R2 * 68;
        const float* A11 = s_w + R3 * 68;
#pragma unroll
        for (int ks = 0; ks < 8; ks++) {
            ab0 |= (A00[tig + 8 * ks]     != 0.0f ? 1u : 0u) << (4 * ks + 0);
            ab0 |= (A01[tig + 8 * ks]     != 0.0f ? 1u : 0u) << (4 * ks + 1);
            ab0 |= (A00[tig + 4 + 8 * ks] != 0.0f ? 1u : 0u) << (4 * ks + 2);
            ab0 |= (A01[tig + 4 + 8 * ks] != 0.0f ? 1u : 0u) << (4 * ks + 3);
            ab1 |= (A10[tig + 8 * ks]     != 0.0f ? 1u : 0u) << (4 * ks + 0);
            ab1 |= (A11[tig + 8 * ks]     != 0.0f ? 1u : 0u) << (4 * ks + 1);
            ab1 |= (A10[tig + 4 + 8 * ks] != 0.0f ? 1u : 0u) << (4 * ks + 2);
            ab1 |= (A11[tig + 4 + 8 * ks] != 0.0f ? 1u : 0u) << (4 * ks + 3);
        }
    }
    __syncthreads();   // adjacency consumed

    // ---- build hi/lo embed tiles in s_w ----
    {
        float4 z = make_float4(0.f, 0.f, 0.f, 0.f);
        float4* zw = (float4*)s_w;
        for (int i = tid; i < 1088; i += NT) zw[i] = z;
    }
    __syncthreads();
    {
        for (int idx = tid; idx < 882; idx += NT) {
            float v = s_h[idx];
            int i = idx / 14, k = idx - i * 14;
            float hi = f2tf(v);
            s_w[i * ET + k] = hi;
            s_w[1088 + i * ET + k] = f2tf(v - hi);
        }
        for (int idx = tid; idx < 896; idx += NT) {
            float v = W_dev[idx];
            int k = idx >> 6, n = idx & 63;
            float hi = f2tf(v);
            s_w[2176 + n * ET + k] = hi;
            s_w[3264 + n * ET + k] = f2tf(v - hi);
        }
    }
    __syncthreads();

    // ---- embed via MMA (hi/lo compensated), 2x2 tiling ----
    {
        const float* oh = s_w;
        const float* ol = s_w + 1088;
        const float* th = s_w + 2176;
        const float* tl = s_w + 3264;
        float c[2][4][4];
#pragma unroll
        for (int mt = 0; mt < 2; mt++)
#pragma unroll
            for (int nt = 0; nt < 4; nt++)
#pragma unroll
                for (int q = 0; q < 4; q++) c[mt][nt][q] = 0.0f;

#pragma unroll
        for (int ks = 0; ks < 2; ks++) {
            int ck = tig + 8 * ks;
            unsigned ah[2][4], al[2][4];
#pragma unroll
            for (int mt = 0; mt < 2; mt++) {
                int ra = rbm + 16 * mt + gid, rb2 = ra + 8;
                ah[mt][0] = __float_as_uint(oh[ra * ET + ck]);
                ah[mt][1] = __float_as_uint(oh[rb2 * ET + ck]);
                ah[mt][2] = __float_as_uint(oh[ra * ET + ck + 4]);
                ah[mt][3] = __float_as_uint(oh[rb2 * ET + ck + 4]);
                al[mt][0] = __float_as_uint(ol[ra * ET + ck]);
                al[mt][1] = __float_as_uint(ol[rb2 * ET + ck]);
                al[mt][2] = __float_as_uint(ol[ra * ET + ck + 4]);
                al[mt][3] = __float_as_uint(ol[rb2 * ET + ck + 4]);
            }
#pragma unroll
            for (int nt = 0; nt < 4; nt++) {
                int n = cbn + gid + 8 * nt;
                unsigned bh0 = __float_as_uint(th[n * ET + ck]);
                unsigned bh1 = __float_as_uint(th[n * ET + ck + 4]);
                unsigned bl0 = __float_as_uint(tl[n * ET + ck]);
                unsigned bl1 = __float_as_uint(tl[n * ET + ck + 4]);
#pragma unroll
                for (int mt = 0; mt < 2; mt++) {
                    mma8(c[mt][nt], ah[mt][0], ah[mt][1], ah[mt][2], ah[mt][3], bh0, bh1);
                    mma8(c[mt][nt], al[mt][0], al[mt][1], al[mt][2], al[mt][3], bh0, bh1);
                    mma8(c[mt][nt], ah[mt][0], ah[mt][1], ah[mt][2], ah[mt][3], bl0, bl1);
                }
            }
        }
        __syncthreads();   // all tile reads done before s_h (obs region) is overwritten
#pragma unroll
        for (int nt = 0; nt < 4; nt++) {
            int j = cbn + 8 * nt + 2 * tig;
            float bx = s_mean[j], by = s_mean[j + 1];
            int pc = j ^ x4;
#pragma unroll
            for (int mt = 0; mt < 2; mt++) {
                int ra = rbm + 16 * mt + gid;
                *(float2*)&s_h[ra * ST + pc] =
                    make_float2(f2tf(fmaxf(c[mt][nt][0] + bx, 0.0f)), f2tf(fmaxf(c[mt][nt][1] + by, 0.0f)));
                *(float2*)&s_h[(ra + 8) * ST + pc] =
                    make_float2(f2tf(fmaxf(c[mt][nt][2] + bx, 0.0f)), f2tf(fmaxf(c[mt][nt][3] + by, 0.0f)));
            }
        }
    }
    __syncthreads();

    // ---- server row fix ; stage W1 ----
    if (tid < 64) {
        float acc = b_srv[tid];
        acc = fmaf(so0, W_srv[tid], acc);
        acc = fmaf(so1, W_srv[64 + tid], acc);
        acc = fmaf(so2, W_srv[128 + tid], acc);
        s_h[63 * ST + (tid ^ 4)] = f2tf(fmaxf(acc, 0.0f));
    }
    stage_cp(s_w, g_wsw, tid);
    __syncthreads();

    const float d0 = s_d[R0], d1 = s_d[R1], d2 = s_d[R2], d3 = s_d[R3];

    // ---- 3 GCN layers ----
#pragma unroll 1
    for (int L = 0; L < 3; L++) {
        float c[2][4][4];
        gemm_ss(s_h, s_w, rbm, cbn, gid, tig, c);              // g = h @ W_L
        __syncthreads();   // FIX: partner warp (same wm) still reads these h rows in its gemm_ss
#pragma unroll
        for (int nt = 0; nt < 4; nt++) {                       // g' = d_k*g
            int pc = (cbn + 8 * nt + 2 * tig) ^ x4;
            *(float2*)&s_h[R0 * ST + pc] = make_float2(f2tf(c[0][nt][0] * d0), f2tf(c[0][nt][1] * d0));
            *(float2*)&s_h[R1 * ST + pc] = make_float2(f2tf(c[0][nt][2] * d1), f2tf(c[0][nt][3] * d1));
            *(float2*)&s_h[R2 * ST + pc] = make_float2(f2tf(c[1][nt][0] * d2), f2tf(c[1][nt][1] * d2));
            *(float2*)&s_h[R3 * ST + pc] = make_float2(f2tf(c[1][nt][2] * d3), f2tf(c[1][nt][3] * d3));
        }
        __syncthreads();

        gemm_rb(ab0, ab1, s_h, cbn, gid, tig, c);              // C2 = adj @ g'
        stage_cp(s_w, g_wsw + (L + 1) * 4608, tid);            // W2, W3, Wf1a
        __syncthreads();

#pragma unroll
        for (int nt = 0; nt < 4; nt++) {                       // h' = relu(d_i*C2 + b_L)
            int j = cbn + 8 * nt + 2 * tig;
            float bx = s_h[(24 + 8 * L + (j >> 3)) * ST + 64 + (j & 7)];
            float by = s_h[(24 + 8 * L + ((j + 1) >> 3)) * ST + 64 + ((j + 1) & 7)];
            int pc = j ^ x4;
            *(float2*)&s_h[R0 * ST + pc] =
                make_float2(f2tf(fmaxf(fmaf(d0, c[0][nt][0], bx), 0.0f)),
                            f2tf(fmaxf(fmaf(d0, c[0][nt][1], by), 0.0f)));
            *(float2*)&s_h[R1 * ST + pc] =
                make_float2(f2tf(fmaxf(fmaf(d1, c[0][nt][2], bx), 0.0f)),
                            f2tf(fmaxf(fmaf(d1, c[0][nt][3], by), 0.0f)));
            *(float2*)&s_h[R2 * ST + pc] =
                make_float2(f2tf(fmaxf(fmaf(d2, c[1][nt][0], bx), 0.0f)),
                            f2tf(fmaxf(fmaf(d2, c[1][nt][1], by), 0.0f)));
            *(float2*)&s_h[R3 * ST + pc] =
                make_float2(f2tf(fmaxf(fmaf(d3, c[1][nt][2], bx), 0.0f)),
                            f2tf(fmaxf(fmaf(d3, c[1][nt][3], by), 0.0f)));
        }
        __syncthreads();   // partner-warp cols needed by next GEMM-A
    }

    // ---- dev_mean ----
    if (tid < 64) {
        float s = 0.0f;
#pragma unroll 7
        for (int r = 0; r < 63; r++) s += s_h[r * ST + (tid ^ (r & 4))];
        s_mean[tid] = s * (1.0f / 63.0f);
    }
    __syncthreads();

    // ---- shared head vector ----
    {
        float acc = bf1[tid];
#pragma unroll 4
        for (int k = 0; k < 64; k++) {
            float srv = s_h[63 * ST + (k ^ 4)];
            acc = fmaf(s_mean[k], Wf1[(64 + k) * 128 + tid], acc);
            acc = fmaf(srv,       Wf1[(128 + k) * 128 + tid], acc);
        }
        s_sh[tid] = acc;
    }
    __syncthreads();

    // ---- head: chunk0 (Wf1a in s_w), restage Wf1b, chunk1 ----
    float pr[4] = {0.0f, 0.0f, 0.0f, 0.0f};
#pragma unroll 1
    for (int c2 = 0; c2 < 2; c2++) {
        float c[2][4][4];
        gemm_ss(s_h, s_w, rbm, cbn, gid, tig, c);
#pragma unroll
        for (int nt = 0; nt < 4; nt++) {
            int col = (c2 << 6) + cbn + (nt << 3) + 2 * tig;
            float2 sh = *(const float2*)&s_sh[col];
            float2 w2 = *(const float2*)&s_w2[col];
            pr[0] = fmaf(fmaxf(c[0][nt][0] + sh.x, 0.0f), w2.x, pr[0]);
            pr[0] = fmaf(fmaxf(c[0][nt][1] + sh.y, 0.0f), w2.y, pr[0]);
            pr[1] = fmaf(fmaxf(c[0][nt][2] + sh.x, 0.0f), w2.x, pr[1]);
            pr[1] = fmaf(fmaxf(c[0][nt][3] + sh.y, 0.0f), w2.y, pr[1]);
            pr[2] = fmaf(fmaxf(c[1][nt][0] + sh.x, 0.0f), w2.x, pr[2]);
            pr[2] = fmaf(fmaxf(c[1][nt][1] + sh.y, 0.0f), w2.y, pr[2]);
            pr[3] = fmaf(fmaxf(c[1][nt][2] + sh.x, 0.0f), w2.x, pr[3]);
            pr[3] = fmaf(fmaxf(c[1][nt][3] + sh.y, 0.0f), w2.y, pr[3]);
        }
        if (c2 == 0) {
            __syncthreads();
            stage_cp(s_w, g_wsw + 4 * 4608, tid);   // Wf1b
            __syncthreads();
        }
    }

    // reduce over tig (4 lanes share rows), then combine the two wn warps via s_mean
#pragma unroll
    for (int off = 1; off < 4; off <<= 1)
#pragma unroll
        for (int r = 0; r < 4; r++)
            pr[r] += __shfl_xor_sync(0xffffffffu, pr[r], off, 4);
    if (wn == 0 && tig == 0) {
        s_mean[R0] = pr[0]; s_mean[R1] = pr[1]; s_mean[R2] = pr[2]; s_mean[R3] = pr[3];
    }
    __syncthreads();
    if (wn == 1 && tig == 0) {
        s_mean[R0] += pr[0]; s_mean[R1] += pr[1]; s_mean[R2] += pr[2]; s_mean[R3] += pr[3];
    }
    __syncthreads();
    if (tid < 63) out[(size_t)b * 63 + tid] = s_mean[tid] + bf2v;
}

extern "C" void kernel_launch(void* const* d_in, const int* in_sizes, int n_in,
                              void* d_out, int out_size)
{
    const float* device_obs = (const float*)d_in[0];
    const float* server_obs = (const float*)d_in[1];
    const float* adjacency  = (const float*)d_in[2];
    const float* W_dev = (const float*)d_in[3];
    const float* b_dev = (const float*)d_in[4];
    const float* W_srv = (const float*)d_in[5];
    const float* b_srv = (const float*)d_in[6];
    const float* W1 = (const float*)d_in[7];
    const float* b1 = (const float*)d_in[8];
    const float* W2 = (const float*)d_in[9];
    const float* b2 = (const float*)d_in[10];
    const float* W3 = (const float*)d_in[11];
    const float* b3 = (const float*)d_in[12];
    const float* Wf1 = (const float*)d_in[13];
    const float* bf1 = (const float*)d_in[14];
    const float* Wf2 = (const float*)d_in[15];
    const float* bf2 = (const float*)d_in[16];

    const int B = in_sizes[0] / (63 * 14);
    prep_kernel<<<(5 * 4608 + 255) / 256, 256>>>(W1, W2, W3, Wf1);
    const size_t smem = 9600 * sizeof(float);
    cudaFuncSetAttribute(pgcn_kernel, cudaFuncAttributeMaxDynamicSharedMemorySize, (int)smem);
    pgcn_kernel<<<B, NT, smem>>>(
        device_obs, server_obs, adjacency,
        W_dev, b_dev, W_srv, b_srv,
        b1, b2, b3, Wf1, bf1, Wf2, bf2,
        (float*)d_out);
}